// round 8
// baseline (speedup 1.0000x reference)
#include <cuda_runtime.h>
#include <math.h>

#define NN 50000
#define EE 800000

// ---------------- scratch (device globals; zero-initialized at load) ----------------
__device__ float g_sae1[EE*4];   // a_edge (conv1) in CSR order
__device__ float g_sae2[EE*4];   // a_edge (conv2) in CSR order
__device__ int   g_ssrc[EE];     // src node in CSR order
__device__ int   g_cnt[NN];      // invariant: zero at kernel_launch entry (scan re-zeroes)
__device__ int   g_cur[NN];
__device__ int   g_rowptr[NN+1];
__device__ float g_h0[NN*128];
__device__ float g_h1[NN*128];
__device__ float g_h2[NN*128];
__device__ float g_xs[NN*128];
__device__ float g_asrc[NN*4];
__device__ float g_adst[NN*4];
__device__ float g_M[32];        // [conv*16 + j*4 + h]
__device__ float g_CW[5*384];    // collapsed classifier: cls_w @ jk_w
__device__ float g_cb2[5];       // collapsed bias

// ---------------- packed f32x2 helpers ----------------
__device__ __forceinline__ unsigned long long pack2(float x){
    unsigned long long r;
    unsigned int u = __float_as_uint(x);
    asm("mov.b64 %0, {%1, %1};" : "=l"(r) : "r"(u));
    return r;
}
__device__ __forceinline__ void fma2(unsigned long long& acc,
                                     unsigned long long a, unsigned long long b){
    asm("fma.rn.f32x2 %0, %1, %2, %0;" : "+l"(acc) : "l"(a), "l"(b));
}
__device__ __forceinline__ float lo2(unsigned long long v){
    unsigned int a, b;
    asm("mov.b64 {%0, %1}, %2;" : "=r"(a), "=r"(b) : "l"(v));
    return __uint_as_float(a);
}
__device__ __forceinline__ float hi2(unsigned long long v){
    unsigned int a, b;
    asm("mov.b64 {%0, %1}, %2;" : "=r"(a), "=r"(b) : "l"(v));
    return __uint_as_float(b);
}

// ============ launch 1: hist + CW-prep + M-prep + node1, fused (R5-proven) ============
#define B_HIST 782
#define B_CW   241
#define B_NODE1 1563

__global__ void __launch_bounds__(256) k_fused1(
        const int* __restrict__ ei,
        const float* __restrict__ le1, const float* __restrict__ ae1,
        const float* __restrict__ le2, const float* __restrict__ ae2,
        const float* __restrict__ cw,  const float* __restrict__ cb,
        const float* __restrict__ jkw, const float* __restrict__ jkb,
        const float* __restrict__ x,
        const float* __restrict__ pw, const float* __restrict__ pb,
        const float* __restrict__ lw,
        const float* __restrict__ asv, const float* __restrict__ adv){
    int b = blockIdx.x;
    if (b < B_HIST){
        int t = b*256 + threadIdx.x;
        if (t < EE/4){
            int4 d4 = ((const int4*)(ei+EE))[t];
            atomicAdd(&g_cnt[d4.x], 1);
            atomicAdd(&g_cnt[d4.y], 1);
            atomicAdd(&g_cnt[d4.z], 1);
            atomicAdd(&g_cnt[d4.w], 1);
        }
        return;
    }
    if (b < B_HIST + B_CW){
        int w = (b-B_HIST)*8 + (threadIdx.x >> 5);
        int lane = threadIdx.x & 31;
        if (w >= 5*385) return;
        int c = w / 385, j = w % 385;
        float4 a = *(const float4*)&cw[c*128 + lane*4];
        int d = lane*4;
        float s;
        if (j < 384){
            s = a.x*jkw[(d+0)*384+j] + a.y*jkw[(d+1)*384+j]
              + a.z*jkw[(d+2)*384+j] + a.w*jkw[(d+3)*384+j];
        } else {
            float4 bb = *(const float4*)&jkb[d];
            s = a.x*bb.x + a.y*bb.y + a.z*bb.z + a.w*bb.w;
        }
        #pragma unroll
        for (int o=16;o>0;o>>=1) s += __shfl_xor_sync(0xffffffffu, s, o);
        if (lane == 0){
            if (j < 384) g_CW[c*384+j] = s;
            else         g_cb2[c] = s + cb[c];
        }
        return;
    }
    if (b == B_HIST + B_CW){
        int t = threadIdx.x;
        if (t < 32){
            int which = t >> 4, j = (t >> 2) & 3, h = t & 3;
            const float* le = which ? le2 : le1;
            const float* ae = which ? ae2 : ae1;
            float s = 0.f;
            for (int c = 0; c < 32; c++)
                s += le[(h*32+c)*4 + j] * ae[h*32+c];
            g_M[which*16 + j*4 + h] = s;
        }
        return;
    }
    // ---- node1: two independent 128-thread halves ----
    __shared__ __align__(16) float sx[2][16*20];
    int tid = threadIdx.x;
    int sub = tid >> 7, stid = tid & 127;
    int n0 = (b - (B_HIST+B_CW+1))*32 + sub*16;
    float attS = asv[stid], attD = adv[stid], pbd = pb[stid];
    float wp[16], wl[16];
    #pragma unroll
    for (int q=0;q<4;q++){
        float4 a = *(const float4*)&pw[stid*16 + q*4];
        wp[q*4+0]=a.x; wp[q*4+1]=a.y; wp[q*4+2]=a.z; wp[q*4+3]=a.w;
        float4 bb = *(const float4*)&lw[stid*16 + q*4];
        wl[q*4+0]=bb.x; wl[q*4+1]=bb.y; wl[q*4+2]=bb.z; wl[q*4+3]=bb.w;
    }
    for (int i=stid;i<256;i+=128){
        int n=i>>4, k=i&15;
        int node=n0+n;
        sx[sub][n*20+k] = (node<NN) ? x[node*16+k] : 0.f;
    }
    __syncthreads();
    float acc0[16], acc1[16];
    #pragma unroll
    for (int n=0;n<16;n++){ acc0[n]=pbd; acc1[n]=0.f; }
    #pragma unroll
    for (int n=0;n<16;n++){
        float4 x0 = *(const float4*)&sx[sub][n*20];
        float4 x1 = *(const float4*)&sx[sub][n*20+4];
        float4 x2 = *(const float4*)&sx[sub][n*20+8];
        float4 x3 = *(const float4*)&sx[sub][n*20+12];
        float xv[16] = {x0.x,x0.y,x0.z,x0.w, x1.x,x1.y,x1.z,x1.w,
                        x2.x,x2.y,x2.z,x2.w, x3.x,x3.y,x3.z,x3.w};
        #pragma unroll
        for (int k=0;k<16;k++){
            acc0[n] = fmaf(xv[k], wp[k], acc0[n]);
            acc1[n] = fmaf(xv[k], wl[k], acc1[n]);
        }
    }
    int lane = stid&31, h = stid>>5;
    for (int n=0;n<16;n++){
        int node=n0+n;
        if (node>=NN) break;
        g_h0[node*128+stid] = acc0[n];
        g_xs[node*128+stid] = acc1[n];
        float s = acc1[n]*attS, dd = acc1[n]*attD;
        #pragma unroll
        for (int o=16;o>0;o>>=1){
            s  += __shfl_down_sync(0xffffffffu, s, o);
            dd += __shfl_down_sync(0xffffffffu, dd, o);
        }
        if (lane==0){ g_asrc[node*4+h]=s; g_adst[node*4+h]=dd; }
    }
}

// ---------------- scan (consumes g_cnt, re-zeroes it for next replay) ----------------
__global__ void k_scan(){
    __shared__ int ssum[1024];
    int t = threadIdx.x;
    int beg = t*49, end = min(beg+49, NN);
    int s = 0;
    for (int i = beg; i < end; i++){ s += g_cnt[i]; }
    ssum[t] = s;
    __syncthreads();
    for (int off = 1; off < 1024; off <<= 1){
        int v = (t >= off) ? ssum[t-off] : 0;
        __syncthreads();
        ssum[t] += v;
        __syncthreads();
    }
    int run = ssum[t] - s;   // exclusive prefix
    for (int i = beg; i < end; i++){
        int c = g_cnt[i];
        g_rowptr[i] = run; g_cur[i] = run;
        g_cnt[i] = 0;                    // restore zero-invariant
        run += c;
    }
    if (t == 1023) g_rowptr[NN] = ssum[1023];
}

// ---------------- edge encoder (R5-proven: 1 edge/thread, vectorized smem) ----------------
__global__ void __launch_bounds__(256) k_edge(
        const float* __restrict__ ea, const int* __restrict__ ei,
        const float* __restrict__ w1, const float* __restrict__ b1,
        const float* __restrict__ w2, const float* __restrict__ b2){
    __shared__ __align__(16) float sw1[256];
    __shared__ float sb1[32];
    __shared__ __align__(16) float sw2t[128];   // [c][h]
    __shared__ float sb2v[4], sM[32];
    int tid = threadIdx.x;
    if (tid < 256) sw1[tid] = w1[tid];
    if (tid < 32)  sb1[tid] = b1[tid];
    if (tid < 128){ int h = tid>>5, c = tid&31; sw2t[c*4+h] = w2[tid]; }
    if (tid < 4)   sb2v[tid] = b2[tid];
    if (tid >= 64 && tid < 96) sM[tid-64] = g_M[tid-64];
    __syncthreads();
    int e = blockIdx.x*256 + tid;
    if (e >= EE) return;
    float4 v0 = ((const float4*)ea)[e*2];
    float4 v1 = ((const float4*)ea)[e*2+1];
    float e0=sb2v[0], e1=sb2v[1], e2=sb2v[2], e3=sb2v[3];
    #pragma unroll
    for (int c=0;c<32;c++){
        float4 wa = *(const float4*)&sw1[c*8];
        float4 wb = *(const float4*)&sw1[c*8+4];
        float hv = sb1[c];
        hv = fmaf(wa.x, v0.x, hv); hv = fmaf(wa.y, v0.y, hv);
        hv = fmaf(wa.z, v0.z, hv); hv = fmaf(wa.w, v0.w, hv);
        hv = fmaf(wb.x, v1.x, hv); hv = fmaf(wb.y, v1.y, hv);
        hv = fmaf(wb.z, v1.z, hv); hv = fmaf(wb.w, v1.w, hv);
        hv = fmaxf(hv, 0.f);
        float4 w2v = *(const float4*)&sw2t[c*4];
        e0 = fmaf(w2v.x, hv, e0);
        e1 = fmaf(w2v.y, hv, e1);
        e2 = fmaf(w2v.z, hv, e2);
        e3 = fmaf(w2v.w, hv, e3);
    }
    float4 r1, r2;
    r1.x = e0*sM[0] + e1*sM[4] + e2*sM[8]  + e3*sM[12];
    r1.y = e0*sM[1] + e1*sM[5] + e2*sM[9]  + e3*sM[13];
    r1.z = e0*sM[2] + e1*sM[6] + e2*sM[10] + e3*sM[14];
    r1.w = e0*sM[3] + e1*sM[7] + e2*sM[11] + e3*sM[15];
    r2.x = e0*sM[16]+ e1*sM[20]+ e2*sM[24] + e3*sM[28];
    r2.y = e0*sM[17]+ e1*sM[21]+ e2*sM[25] + e3*sM[29];
    r2.z = e0*sM[18]+ e1*sM[22]+ e2*sM[26] + e3*sM[30];
    r2.w = e0*sM[19]+ e1*sM[23]+ e2*sM[27] + e3*sM[31];
    int srcn = ei[e], d = ei[EE+e];
    int pos = atomicAdd(&g_cur[d], 1);
    g_ssrc[pos] = srcn;
    ((float4*)g_sae1)[pos] = r1;
    ((float4*)g_sae2)[pos] = r2;
}

// ---------------- fused GAT conv: packed (offset,weight) smem (R7-proven) ----------------
__global__ void __launch_bounds__(512) k_gat(const float* __restrict__ bias,
                      const float* __restrict__ gam,
                      const float* __restrict__ bet, int conv){
    __shared__ float2 sp[16][132];   // [warp][h*33 + j], stride 33 => conflict-free
    int wid = threadIdx.x >> 5, lane = threadIdx.x & 31;
    int node = blockIdx.x*16 + wid;
    if (node >= NN) return;
    int h = lane >> 3;
    const float4* __restrict__ sae   = (const float4*)(conv ? g_sae2 : g_sae1);
    const float4* __restrict__ asrc4 = (const float4*)g_asrc;
    const char*   xbase = ((const char*)g_xs) + lane*16;
    float4 ad = ((const float4*)g_adst)[node];
    int beg = g_rowptr[node], end = g_rowptr[node+1];
    float4 den = make_float4(0.f,0.f,0.f,0.f);
    float4 acc = make_float4(0.f,0.f,0.f,0.f);
    for (int base = beg; base < end; base += 32){
        int idx = base + lane;
        bool v = idx < end;
        int s = g_ssrc[v ? idx : end-1];
        float4 w = make_float4(0.f,0.f,0.f,0.f);
        if (v){
            float4 ae = sae[idx];
            float4 as = asrc4[s];
            float ax = as.x+ad.x+ae.x; ax = ax>0.f?ax:0.2f*ax;
            float ay = as.y+ad.y+ae.y; ay = ay>0.f?ay:0.2f*ay;
            float az = as.z+ad.z+ae.z; az = az>0.f?az:0.2f*az;
            float aw = as.w+ad.w+ae.w; aw = aw>0.f?aw:0.2f*aw;
            w = make_float4(__expf(ax), __expf(ay), __expf(az), __expf(aw));
        }
        den.x += w.x; den.y += w.y; den.z += w.z; den.w += w.w;
        float so = __uint_as_float((unsigned)s * 512u);
        __syncwarp();
        sp[wid][lane]       = make_float2(so, w.x);
        sp[wid][33 + lane]  = make_float2(so, w.y);
        sp[wid][66 + lane]  = make_float2(so, w.z);
        sp[wid][99 + lane]  = make_float2(so, w.w);
        __syncwarp();
        int cnt = end - base; if (cnt > 32) cnt = 32;
        const float2* hp2 = &sp[wid][h*33];
        for (int c = 0; c < cnt; c += 8){
            #pragma unroll
            for (int j = 0; j < 8; j++){
                float2 e2 = hp2[c+j];
                float4 xv = *(const float4*)(xbase + __float_as_uint(e2.x));
                acc.x = fmaf(e2.y, xv.x, acc.x);
                acc.y = fmaf(e2.y, xv.y, acc.y);
                acc.z = fmaf(e2.y, xv.z, acc.z);
                acc.w = fmaf(e2.y, xv.w, acc.w);
            }
        }
    }
    #pragma unroll
    for (int o=16;o>0;o>>=1){
        den.x += __shfl_xor_sync(0xffffffffu, den.x, o);
        den.y += __shfl_xor_sync(0xffffffffu, den.y, o);
        den.z += __shfl_xor_sync(0xffffffffu, den.z, o);
        den.w += __shfl_xor_sync(0xffffffffu, den.w, o);
    }
    float dh = (h==0)?den.x:(h==1)?den.y:(h==2)?den.z:den.w;
    float inv = 1.f/(dh + 1e-16f);
    const float* hp = conv ? g_h1 : g_h0;
    float*       ho = conv ? g_h2 : g_h1;
    float4 hv = ((const float4*)hp)[node*32+lane];
    float4 bv = *(const float4*)&bias[lane*4];
    float4 r;
    r.x = acc.x*inv + bv.x; r.x = (r.x>0.f)?r.x:(__expf(r.x)-1.f); r.x += hv.x;
    r.y = acc.y*inv + bv.y; r.y = (r.y>0.f)?r.y:(__expf(r.y)-1.f); r.y += hv.y;
    r.z = acc.z*inv + bv.z; r.z = (r.z>0.f)?r.z:(__expf(r.z)-1.f); r.z += hv.z;
    r.w = acc.w*inv + bv.w; r.w = (r.w>0.f)?r.w:(__expf(r.w)-1.f); r.w += hv.w;
    float s1 = r.x+r.y+r.z+r.w;
    float s2 = r.x*r.x + r.y*r.y + r.z*r.z + r.w*r.w;
    #pragma unroll
    for (int o=16;o>0;o>>=1){
        s1 += __shfl_xor_sync(0xffffffffu, s1, o);
        s2 += __shfl_xor_sync(0xffffffffu, s2, o);
    }
    float mu  = s1 * (1.f/128.f);
    float var = s2 * (1.f/128.f) - mu*mu;
    float rs  = rsqrtf(var + 1e-5f);
    float4 gv = *(const float4*)&gam[lane*4];
    float4 be = *(const float4*)&bet[lane*4];
    float4 o4;
    o4.x = (r.x-mu)*rs*gv.x + be.x;
    o4.y = (r.y-mu)*rs*gv.y + be.y;
    o4.z = (r.z-mu)*rs*gv.z + be.z;
    o4.w = (r.w-mu)*rs*gv.w + be.w;
    ((float4*)ho)[node*32+lane] = o4;
}

// ---------------- conv2 GEMM + fused attention dots ----------------
__global__ void __launch_bounds__(256) k_node2(const float* __restrict__ lin,
                                               const float* __restrict__ asv,
                                               const float* __restrict__ adv){
    __shared__ float sA[16*132];
    __shared__ float sB[16*132];
    int tid = threadIdx.x;
    int tx = tid & 15, ty = tid >> 4;
    int n0 = blockIdx.x*128;
    unsigned long long acc[8][4];
    #pragma unroll
    for (int r=0;r<8;r++)
        #pragma unroll
        for (int p=0;p<4;p++) acc[r][p] = 0ULL;
    for (int kc=0;kc<8;kc++){
        __syncthreads();
        #pragma unroll
        for (int t=tid;t<512;t+=256){
            int r = t>>2, q = t&3;
            int node = n0 + r;
            float4 v = (node<NN) ? *(const float4*)&g_h1[node*128 + kc*16 + q*4]
                                 : make_float4(0.f,0.f,0.f,0.f);
            sA[(q*4+0)*132+r]=v.x; sA[(q*4+1)*132+r]=v.y;
            sA[(q*4+2)*132+r]=v.z; sA[(q*4+3)*132+r]=v.w;
        }
        #pragma unroll
        for (int t=tid;t<512;t+=256){
            int d = t>>2, q = t&3;
            float4 v = *(const float4*)&lin[d*128 + kc*16 + q*4];
            sB[(q*4+0)*132+d]=v.x; sB[(q*4+1)*132+d]=v.y;
            sB[(q*4+2)*132+d]=v.z; sB[(q*4+3)*132+d]=v.w;
        }
        __syncthreads();
        #pragma unroll
        for (int k=0;k<16;k++){
            float4 a0 = *(const float4*)&sA[k*132 + ty*8];
            float4 a1 = *(const float4*)&sA[k*132 + ty*8 + 4];
            ulonglong2 b0 = *(const ulonglong2*)&sB[k*132 + tx*8];
            ulonglong2 b1 = *(const ulonglong2*)&sB[k*132 + tx*8 + 4];
            unsigned long long bp0=b0.x, bp1=b0.y, bp2=b1.x, bp3=b1.y;
            float ar[8] = {a0.x,a0.y,a0.z,a0.w,a1.x,a1.y,a1.z,a1.w};
            #pragma unroll
            for (int r=0;r<8;r++){
                unsigned long long a2 = pack2(ar[r]);
                fma2(acc[r][0], a2, bp0);
                fma2(acc[r][1], a2, bp1);
                fma2(acc[r][2], a2, bp2);
                fma2(acc[r][3], a2, bp3);
            }
        }
    }
    float4 ws0 = *(const float4*)&asv[tx*8];
    float4 ws1 = *(const float4*)&asv[tx*8+4];
    float4 wd0 = *(const float4*)&adv[tx*8];
    float4 wd1 = *(const float4*)&adv[tx*8+4];
    int hh = tx >> 2;
    #pragma unroll
    for (int r=0;r<8;r++){
        int node = n0 + ty*8 + r;
        if (node < NN){
            float f0=lo2(acc[r][0]), f1=hi2(acc[r][0]);
            float f2=lo2(acc[r][1]), f3=hi2(acc[r][1]);
            float f4=lo2(acc[r][2]), f5=hi2(acc[r][2]);
            float f6=lo2(acc[r][3]), f7=hi2(acc[r][3]);
            ulonglong2 v0; v0.x = acc[r][0]; v0.y = acc[r][1];
            ulonglong2 v1; v1.x = acc[r][2]; v1.y = acc[r][3];
            *(ulonglong2*)&g_xs[node*128 + tx*8]     = v0;
            *(ulonglong2*)&g_xs[node*128 + tx*8 + 4] = v1;
            float s = f0*ws0.x + f1*ws0.y + f2*ws0.z + f3*ws0.w
                    + f4*ws1.x + f5*ws1.y + f6*ws1.z + f7*ws1.w;
            float d = f0*wd0.x + f1*wd0.y + f2*wd0.z + f3*wd0.w
                    + f4*wd1.x + f5*wd1.y + f6*wd1.z + f7*wd1.w;
            s += __shfl_xor_sync(0xffffffffu, s, 1);
            s += __shfl_xor_sync(0xffffffffu, s, 2);
            d += __shfl_xor_sync(0xffffffffu, d, 1);
            d += __shfl_xor_sync(0xffffffffu, d, 2);
            if ((tx & 3) == 0){
                g_asrc[node*4+hh] = s;
                g_adst[node*4+hh] = d;
            }
        }
    }
}

// ---------------- collapsed output: logits + log_softmax ----------------
__global__ void k_out(float* __restrict__ out){
    __shared__ float sCW[5*384];
    __shared__ float sCB[5];
    int tid = threadIdx.x;
    for (int i=tid;i<1920;i+=256) sCW[i] = g_CW[i];
    if (tid < 5) sCB[tid] = g_cb2[tid];
    __syncthreads();
    int node = blockIdx.x*8 + (tid>>5);
    if (node >= NN) return;
    int lane = tid & 31;
    float4 a0 = ((const float4*)g_h0)[node*32+lane];
    float4 a1 = ((const float4*)g_h1)[node*32+lane];
    float4 a2 = ((const float4*)g_h2)[node*32+lane];
    float lg[5];
    #pragma unroll
    for (int c=0;c<5;c++){
        const float* w = &sCW[c*384];
        float4 b0 = *(const float4*)&w[lane*4];
        float4 b1 = *(const float4*)&w[128 + lane*4];
        float4 b2 = *(const float4*)&w[256 + lane*4];
        float p = a0.x*b0.x + a0.y*b0.y + a0.z*b0.z + a0.w*b0.w;
        p = fmaf(a1.x,b1.x, fmaf(a1.y,b1.y, fmaf(a1.z,b1.z, fmaf(a1.w,b1.w, p))));
        p = fmaf(a2.x,b2.x, fmaf(a2.y,b2.y, fmaf(a2.z,b2.z, fmaf(a2.w,b2.w, p))));
        #pragma unroll
        for (int o=16;o>0;o>>=1) p += __shfl_xor_sync(0xffffffffu, p, o);
        lg[c] = p + sCB[c];
    }
    if (lane == 0){
        float m = lg[0];
        #pragma unroll
        for (int c=1;c<5;c++) m = fmaxf(m, lg[c]);
        float s = 0.f;
        #pragma unroll
        for (int c=0;c<5;c++) s += __expf(lg[c]-m);
        float ls = logf(s);
        #pragma unroll
        for (int c=0;c<5;c++) out[node*5+c] = lg[c]-m-ls;
    }
}

// ---------------- launcher ----------------
extern "C" void kernel_launch(void* const* d_in, const int* in_sizes, int n_in,
                              void* d_out, int out_size){
    const float* x      = (const float*)d_in[0];
    const int*   ei     = (const int*)  d_in[1];
    const float* ea     = (const float*)d_in[2];
    const float* ee_w1  = (const float*)d_in[3];
    const float* ee_b1  = (const float*)d_in[4];
    const float* ee_w2  = (const float*)d_in[5];
    const float* ee_b2  = (const float*)d_in[6];
    const float* proj_w = (const float*)d_in[7];
    const float* proj_b = (const float*)d_in[8];
    const float* c1_lin = (const float*)d_in[9];
    const float* c1_as  = (const float*)d_in[10];
    const float* c1_ad  = (const float*)d_in[11];
    const float* c1_le  = (const float*)d_in[12];
    const float* c1_ae  = (const float*)d_in[13];
    const float* c1_b   = (const float*)d_in[14];
    const float* c2_lin = (const float*)d_in[15];
    const float* c2_as  = (const float*)d_in[16];
    const float* c2_ad  = (const float*)d_in[17];
    const float* c2_le  = (const float*)d_in[18];
    const float* c2_ae  = (const float*)d_in[19];
    const float* c2_b   = (const float*)d_in[20];
    const float* n1_g   = (const float*)d_in[21];
    const float* n1_b   = (const float*)d_in[22];
    const float* n2_g   = (const float*)d_in[23];
    const float* n2_b   = (const float*)d_in[24];
    const float* jk_w   = (const float*)d_in[25];
    const float* jk_b   = (const float*)d_in[26];
    const float* cls_w  = (const float*)d_in[27];
    const float* cls_b  = (const float*)d_in[28];
    float* out = (float*)d_out;

    k_fused1<<<B_HIST+B_CW+1+B_NODE1,256>>>(ei, c1_le, c1_ae, c2_le, c2_ae,
                                            cls_w, cls_b, jk_w, jk_b,
                                            x, proj_w, proj_b, c1_lin, c1_as, c1_ad);
    k_scan<<<1,1024>>>();
    k_edge<<<(EE+255)/256,256>>>(ea, ei, ee_w1, ee_b1, ee_w2, ee_b2);
    k_gat<<<(NN+15)/16,512>>>(c1_b, n1_g, n1_b, 0);      // profiled slot (4th)
    k_node2<<<(NN+127)/128,256>>>(c2_lin, c2_as, c2_ad);
    k_gat<<<(NN+15)/16,512>>>(c2_b, n2_g, n2_b, 1);
    k_out<<<(NN+7)/8,256>>>(out);
}

// round 9
// speedup vs baseline: 1.3332x; 1.3332x over previous
#include <cuda_runtime.h>
#include <math.h>

#define NN 50000
#define EE 800000

// ---------------- scratch (device globals; zero-initialized at load) ----------------
__device__ float g_sae1[EE*4];   // a_edge (conv1) in CSR order
__device__ float g_sae2[EE*4];   // a_edge (conv2) in CSR order
__device__ int   g_ssrc[EE];     // src node in CSR order
__device__ int   g_cnt[NN];      // invariant: zero at kernel_launch entry (scanc re-zeroes)
__device__ int   g_cur[NN];
__device__ int   g_rowptr[NN+1];
__device__ int   g_part[128];
__device__ float g_h0[NN*128];
__device__ float g_h1[NN*128];
__device__ float g_h2[NN*128];
__device__ float g_xs[NN*128];
__device__ float g_asrc[NN*4];
__device__ float g_adst[NN*4];
__device__ float g_M[32];        // [conv*16 + j*4 + h]
__device__ float g_CW[5*384];    // collapsed classifier: cls_w @ jk_w
__device__ float g_cb2[5];       // collapsed bias

// ---------------- packed f32x2 helpers ----------------
__device__ __forceinline__ unsigned long long pack2(float x){
    unsigned long long r;
    unsigned int u = __float_as_uint(x);
    asm("mov.b64 %0, {%1, %1};" : "=l"(r) : "r"(u));
    return r;
}
__device__ __forceinline__ void fma2(unsigned long long& acc,
                                     unsigned long long a, unsigned long long b){
    asm("fma.rn.f32x2 %0, %1, %2, %0;" : "+l"(acc) : "l"(a), "l"(b));
}
__device__ __forceinline__ float lo2(unsigned long long v){
    unsigned int a, b;
    asm("mov.b64 {%0, %1}, %2;" : "=r"(a), "=r"(b) : "l"(v));
    return __uint_as_float(a);
}
__device__ __forceinline__ float hi2(unsigned long long v){
    unsigned int a, b;
    asm("mov.b64 {%0, %1}, %2;" : "=r"(a), "=r"(b) : "l"(v));
    return __uint_as_float(b);
}

// ============ launch 1: hist + CW-prep + M-prep + node1, fused ============
#define B_HIST 782
#define B_CW   241
#define B_NODE1 1563

__global__ void __launch_bounds__(256) k_fused1(
        const int* __restrict__ ei,
        const float* __restrict__ le1, const float* __restrict__ ae1,
        const float* __restrict__ le2, const float* __restrict__ ae2,
        const float* __restrict__ cw,  const float* __restrict__ cb,
        const float* __restrict__ jkw, const float* __restrict__ jkb,
        const float* __restrict__ x,
        const float* __restrict__ pw, const float* __restrict__ pb,
        const float* __restrict__ lw,
        const float* __restrict__ asv, const float* __restrict__ adv){
    int b = blockIdx.x;
    if (b < B_HIST){
        int t = b*256 + threadIdx.x;
        if (t < EE/4){
            int4 d4 = ((const int4*)(ei+EE))[t];
            atomicAdd(&g_cnt[d4.x], 1);
            atomicAdd(&g_cnt[d4.y], 1);
            atomicAdd(&g_cnt[d4.z], 1);
            atomicAdd(&g_cnt[d4.w], 1);
        }
        return;
    }
    if (b < B_HIST + B_CW){
        int w = (b-B_HIST)*8 + (threadIdx.x >> 5);
        int lane = threadIdx.x & 31;
        if (w >= 5*385) return;
        int c = w / 385, j = w % 385;
        float4 a = *(const float4*)&cw[c*128 + lane*4];
        int d = lane*4;
        float s;
        if (j < 384){
            s = a.x*jkw[(d+0)*384+j] + a.y*jkw[(d+1)*384+j]
              + a.z*jkw[(d+2)*384+j] + a.w*jkw[(d+3)*384+j];
        } else {
            float4 bb = *(const float4*)&jkb[d];
            s = a.x*bb.x + a.y*bb.y + a.z*bb.z + a.w*bb.w;
        }
        #pragma unroll
        for (int o=16;o>0;o>>=1) s += __shfl_xor_sync(0xffffffffu, s, o);
        if (lane == 0){
            if (j < 384) g_CW[c*384+j] = s;
            else         g_cb2[c] = s + cb[c];
        }
        return;
    }
    if (b == B_HIST + B_CW){
        int t = threadIdx.x;
        if (t < 32){
            int which = t >> 4, j = (t >> 2) & 3, h = t & 3;
            const float* le = which ? le2 : le1;
            const float* ae = which ? ae2 : ae1;
            float s = 0.f;
            for (int c = 0; c < 32; c++)
                s += le[(h*32+c)*4 + j] * ae[h*32+c];
            g_M[which*16 + j*4 + h] = s;
        }
        return;
    }
    // ---- node1: two independent 128-thread halves ----
    __shared__ __align__(16) float sx[2][16*20];
    int tid = threadIdx.x;
    int sub = tid >> 7, stid = tid & 127;
    int n0 = (b - (B_HIST+B_CW+1))*32 + sub*16;
    float attS = asv[stid], attD = adv[stid], pbd = pb[stid];
    float wp[16], wl[16];
    #pragma unroll
    for (int q=0;q<4;q++){
        float4 a = *(const float4*)&pw[stid*16 + q*4];
        wp[q*4+0]=a.x; wp[q*4+1]=a.y; wp[q*4+2]=a.z; wp[q*4+3]=a.w;
        float4 bb = *(const float4*)&lw[stid*16 + q*4];
        wl[q*4+0]=bb.x; wl[q*4+1]=bb.y; wl[q*4+2]=bb.z; wl[q*4+3]=bb.w;
    }
    for (int i=stid;i<256;i+=128){
        int n=i>>4, k=i&15;
        int node=n0+n;
        sx[sub][n*20+k] = (node<NN) ? x[node*16+k] : 0.f;
    }
    __syncthreads();
    float acc0[16], acc1[16];
    #pragma unroll
    for (int n=0;n<16;n++){ acc0[n]=pbd; acc1[n]=0.f; }
    #pragma unroll
    for (int n=0;n<16;n++){
        float4 x0 = *(const float4*)&sx[sub][n*20];
        float4 x1 = *(const float4*)&sx[sub][n*20+4];
        float4 x2 = *(const float4*)&sx[sub][n*20+8];
        float4 x3 = *(const float4*)&sx[sub][n*20+12];
        float xv[16] = {x0.x,x0.y,x0.z,x0.w, x1.x,x1.y,x1.z,x1.w,
                        x2.x,x2.y,x2.z,x2.w, x3.x,x3.y,x3.z,x3.w};
        #pragma unroll
        for (int k=0;k<16;k++){
            acc0[n] = fmaf(xv[k], wp[k], acc0[n]);
            acc1[n] = fmaf(xv[k], wl[k], acc1[n]);
        }
    }
    int lane = stid&31, h = stid>>5;
    for (int n=0;n<16;n++){
        int node=n0+n;
        if (node>=NN) break;
        g_h0[node*128+stid] = acc0[n];
        g_xs[node*128+stid] = acc1[n];
        float s = acc1[n]*attS, dd = acc1[n]*attD;
        #pragma unroll
        for (int o=16;o>0;o>>=1){
            s  += __shfl_down_sync(0xffffffffu, s, o);
            dd += __shfl_down_sync(0xffffffffu, dd, o);
        }
        if (lane==0){ g_asrc[node*4+h]=s; g_adst[node*4+h]=dd; }
    }
}

// ---------------- multi-block scan (3 tiny kernels) ----------------
__global__ void __launch_bounds__(512) k_scana(){
    __shared__ int sred[16];
    int t = blockIdx.x*512 + threadIdx.x;
    int v = (t < NN) ? g_cnt[t] : 0;
    #pragma unroll
    for (int o=16;o>0;o>>=1) v += __shfl_xor_sync(0xffffffffu, v, o);
    int lane = threadIdx.x & 31, wid = threadIdx.x >> 5;
    if (lane == 0) sred[wid] = v;
    __syncthreads();
    if (threadIdx.x < 16){
        v = sred[threadIdx.x];
        #pragma unroll
        for (int o=8;o>0;o>>=1) v += __shfl_xor_sync(0xffffu, v, o);
        if (threadIdx.x == 0) g_part[blockIdx.x] = v;
    }
}

__global__ void __launch_bounds__(128) k_scanb(){
    __shared__ int s[128];
    int t = threadIdx.x;
    int v = (t < 98) ? g_part[t] : 0;
    s[t] = v;
    __syncthreads();
    for (int off=1; off<128; off<<=1){
        int u = (t >= off) ? s[t-off] : 0;
        __syncthreads();
        s[t] += u;
        __syncthreads();
    }
    if (t < 98) g_part[t] = s[t] - v;   // exclusive
}

__global__ void __launch_bounds__(512) k_scanc(){
    __shared__ int s[512];
    int t = blockIdx.x*512 + threadIdx.x;
    int v = (t < NN) ? g_cnt[t] : 0;
    s[threadIdx.x] = v;
    __syncthreads();
    for (int off=1; off<512; off<<=1){
        int u = (threadIdx.x >= off) ? s[threadIdx.x-off] : 0;
        __syncthreads();
        s[threadIdx.x] += u;
        __syncthreads();
    }
    int excl = s[threadIdx.x] - v + g_part[blockIdx.x];
    if (t < NN){
        g_rowptr[t] = excl;
        g_cur[t]    = excl;
        g_cnt[t]    = 0;                // restore zero-invariant for graph replay
        if (t == NN-1) g_rowptr[NN] = excl + v;
    }
}

// ---------------- edge encoder: 4 edges/thread, WM-folded, coalesced ----------------
#define QSTRIDE 200000   // EE/4
__global__ void __launch_bounds__(256) k_edge(
        const float* __restrict__ ea, const int* __restrict__ ei,
        const float* __restrict__ w1, const float* __restrict__ b1,
        const float* __restrict__ w2, const float* __restrict__ b2){
    __shared__ __align__(16) float sw1[256];
    __shared__ float sb1[32];
    __shared__ __align__(16) float sWM1[128];  // [c][h] = sum_j w2[j][c]*M1[j][h]
    __shared__ __align__(16) float sWM2[128];
    __shared__ float sR0[8];                   // b2 @ M1, b2 @ M2
    int tid = threadIdx.x;
    if (tid < 256) sw1[tid] = w1[tid];
    if (tid < 32)  sb1[tid] = b1[tid];
    if (tid < 128){
        int c = tid >> 2, h = tid & 3;
        float s1 = 0.f, s2 = 0.f;
        #pragma unroll
        for (int j=0;j<4;j++){
            float wv = w2[j*32+c];
            s1 = fmaf(wv, g_M[j*4+h],    s1);
            s2 = fmaf(wv, g_M[16+j*4+h], s2);
        }
        sWM1[c*4+h] = s1;
        sWM2[c*4+h] = s2;
    }
    if (tid >= 128 && tid < 136){
        int which = (tid-128) >> 2, h = tid & 3;
        float s = 0.f;
        #pragma unroll
        for (int j=0;j<4;j++) s = fmaf(b2[j], g_M[which*16+j*4+h], s);
        sR0[tid-128] = s;
    }
    __syncthreads();
    int gid = blockIdx.x*256 + tid;
    if (gid >= QSTRIDE) return;
    // 4 edges: gid, gid+Q, gid+2Q, gid+3Q — each q fully coalesced across lanes
    float4 A[4][2];
    #pragma unroll
    for (int q=0;q<4;q++){
        int e = gid + q*QSTRIDE;
        A[q][0] = ((const float4*)ea)[e*2];
        A[q][1] = ((const float4*)ea)[e*2+1];
    }
    float4 R10 = *(const float4*)&sR0[0];
    float4 R20 = *(const float4*)&sR0[4];
    float4 r1[4], r2[4];
    #pragma unroll
    for (int q=0;q<4;q++){ r1[q]=R10; r2[q]=R20; }
    #pragma unroll
    for (int c=0;c<32;c++){
        float4 wa = *(const float4*)&sw1[c*8];
        float4 wb = *(const float4*)&sw1[c*8+4];
        float bc  = sb1[c];
        float4 m1 = *(const float4*)&sWM1[c*4];
        float4 m2 = *(const float4*)&sWM2[c*4];
        #pragma unroll
        for (int q=0;q<4;q++){
            float hv = bc;
            hv = fmaf(wa.x, A[q][0].x, hv); hv = fmaf(wa.y, A[q][0].y, hv);
            hv = fmaf(wa.z, A[q][0].z, hv); hv = fmaf(wa.w, A[q][0].w, hv);
            hv = fmaf(wb.x, A[q][1].x, hv); hv = fmaf(wb.y, A[q][1].y, hv);
            hv = fmaf(wb.z, A[q][1].z, hv); hv = fmaf(wb.w, A[q][1].w, hv);
            hv = fmaxf(hv, 0.f);
            r1[q].x = fmaf(m1.x, hv, r1[q].x);
            r1[q].y = fmaf(m1.y, hv, r1[q].y);
            r1[q].z = fmaf(m1.z, hv, r1[q].z);
            r1[q].w = fmaf(m1.w, hv, r1[q].w);
            r2[q].x = fmaf(m2.x, hv, r2[q].x);
            r2[q].y = fmaf(m2.y, hv, r2[q].y);
            r2[q].z = fmaf(m2.z, hv, r2[q].z);
            r2[q].w = fmaf(m2.w, hv, r2[q].w);
        }
    }
    #pragma unroll
    for (int q=0;q<4;q++){
        int e = gid + q*QSTRIDE;
        int srcn = ei[e], d = ei[EE+e];
        int pos = atomicAdd(&g_cur[d], 1);
        g_ssrc[pos] = srcn;
        ((float4*)g_sae1)[pos] = r1[q];
        ((float4*)g_sae2)[pos] = r2[q];
    }
}

// ---------------- fused GAT conv: packed (offset,weight) smem (R7-proven) ----------------
__global__ void __launch_bounds__(512) k_gat(const float* __restrict__ bias,
                      const float* __restrict__ gam,
                      const float* __restrict__ bet, int conv){
    __shared__ float2 sp[16][132];   // [warp][h*33 + j], stride 33 => conflict-free
    int wid = threadIdx.x >> 5, lane = threadIdx.x & 31;
    int node = blockIdx.x*16 + wid;
    if (node >= NN) return;
    int h = lane >> 3;
    const float4* __restrict__ sae   = (const float4*)(conv ? g_sae2 : g_sae1);
    const float4* __restrict__ asrc4 = (const float4*)g_asrc;
    const char*   xbase = ((const char*)g_xs) + lane*16;
    float4 ad = ((const float4*)g_adst)[node];
    int beg = g_rowptr[node], end = g_rowptr[node+1];
    float4 den = make_float4(0.f,0.f,0.f,0.f);
    float4 acc = make_float4(0.f,0.f,0.f,0.f);
    for (int base = beg; base < end; base += 32){
        int idx = base + lane;
        bool v = idx < end;
        int s = g_ssrc[v ? idx : end-1];
        float4 w = make_float4(0.f,0.f,0.f,0.f);
        if (v){
            float4 ae = sae[idx];
            float4 as = asrc4[s];
            float ax = as.x+ad.x+ae.x; ax = ax>0.f?ax:0.2f*ax;
            float ay = as.y+ad.y+ae.y; ay = ay>0.f?ay:0.2f*ay;
            float az = as.z+ad.z+ae.z; az = az>0.f?az:0.2f*az;
            float aw = as.w+ad.w+ae.w; aw = aw>0.f?aw:0.2f*aw;
            w = make_float4(__expf(ax), __expf(ay), __expf(az), __expf(aw));
        }
        den.x += w.x; den.y += w.y; den.z += w.z; den.w += w.w;
        float so = __uint_as_float((unsigned)s * 512u);
        __syncwarp();
        sp[wid][lane]       = make_float2(so, w.x);
        sp[wid][33 + lane]  = make_float2(so, w.y);
        sp[wid][66 + lane]  = make_float2(so, w.z);
        sp[wid][99 + lane]  = make_float2(so, w.w);
        __syncwarp();
        int cnt = end - base; if (cnt > 32) cnt = 32;
        const float2* hp2 = &sp[wid][h*33];
        for (int c = 0; c < cnt; c += 8){
            #pragma unroll
            for (int j = 0; j < 8; j++){
                float2 e2 = hp2[c+j];
                float4 xv = *(const float4*)(xbase + __float_as_uint(e2.x));
                acc.x = fmaf(e2.y, xv.x, acc.x);
                acc.y = fmaf(e2.y, xv.y, acc.y);
                acc.z = fmaf(e2.y, xv.z, acc.z);
                acc.w = fmaf(e2.y, xv.w, acc.w);
            }
        }
    }
    #pragma unroll
    for (int o=16;o>0;o>>=1){
        den.x += __shfl_xor_sync(0xffffffffu, den.x, o);
        den.y += __shfl_xor_sync(0xffffffffu, den.y, o);
        den.z += __shfl_xor_sync(0xffffffffu, den.z, o);
        den.w += __shfl_xor_sync(0xffffffffu, den.w, o);
    }
    float dh = (h==0)?den.x:(h==1)?den.y:(h==2)?den.z:den.w;
    float inv = 1.f/(dh + 1e-16f);
    const float* hp = conv ? g_h1 : g_h0;
    float*       ho = conv ? g_h2 : g_h1;
    float4 hv = ((const float4*)hp)[node*32+lane];
    float4 bv = *(const float4*)&bias[lane*4];
    float4 r;
    r.x = acc.x*inv + bv.x; r.x = (r.x>0.f)?r.x:(__expf(r.x)-1.f); r.x += hv.x;
    r.y = acc.y*inv + bv.y; r.y = (r.y>0.f)?r.y:(__expf(r.y)-1.f); r.y += hv.y;
    r.z = acc.z*inv + bv.z; r.z = (r.z>0.f)?r.z:(__expf(r.z)-1.f); r.z += hv.z;
    r.w = acc.w*inv + bv.w; r.w = (r.w>0.f)?r.w:(__expf(r.w)-1.f); r.w += hv.w;
    float s1 = r.x+r.y+r.z+r.w;
    float s2 = r.x*r.x + r.y*r.y + r.z*r.z + r.w*r.w;
    #pragma unroll
    for (int o=16;o>0;o>>=1){
        s1 += __shfl_xor_sync(0xffffffffu, s1, o);
        s2 += __shfl_xor_sync(0xffffffffu, s2, o);
    }
    float mu  = s1 * (1.f/128.f);
    float var = s2 * (1.f/128.f) - mu*mu;
    float rs  = rsqrtf(var + 1e-5f);
    float4 gv = *(const float4*)&gam[lane*4];
    float4 be = *(const float4*)&bet[lane*4];
    float4 o4;
    o4.x = (r.x-mu)*rs*gv.x + be.x;
    o4.y = (r.y-mu)*rs*gv.y + be.y;
    o4.z = (r.z-mu)*rs*gv.z + be.z;
    o4.w = (r.w-mu)*rs*gv.w + be.w;
    ((float4*)ho)[node*32+lane] = o4;
}

// ---------------- conv2 GEMM + fused attention dots ----------------
__global__ void __launch_bounds__(256) k_node2(const float* __restrict__ lin,
                                               const float* __restrict__ asv,
                                               const float* __restrict__ adv){
    __shared__ float sA[16*132];
    __shared__ float sB[16*132];
    int tid = threadIdx.x;
    int tx = tid & 15, ty = tid >> 4;
    int n0 = blockIdx.x*128;
    unsigned long long acc[8][4];
    #pragma unroll
    for (int r=0;r<8;r++)
        #pragma unroll
        for (int p=0;p<4;p++) acc[r][p] = 0ULL;
    for (int kc=0;kc<8;kc++){
        __syncthreads();
        #pragma unroll
        for (int t=tid;t<512;t+=256){
            int r = t>>2, q = t&3;
            int node = n0 + r;
            float4 v = (node<NN) ? *(const float4*)&g_h1[node*128 + kc*16 + q*4]
                                 : make_float4(0.f,0.f,0.f,0.f);
            sA[(q*4+0)*132+r]=v.x; sA[(q*4+1)*132+r]=v.y;
            sA[(q*4+2)*132+r]=v.z; sA[(q*4+3)*132+r]=v.w;
        }
        #pragma unroll
        for (int t=tid;t<512;t+=256){
            int d = t>>2, q = t&3;
            float4 v = *(const float4*)&lin[d*128 + kc*16 + q*4];
            sB[(q*4+0)*132+d]=v.x; sB[(q*4+1)*132+d]=v.y;
            sB[(q*4+2)*132+d]=v.z; sB[(q*4+3)*132+d]=v.w;
        }
        __syncthreads();
        #pragma unroll
        for (int k=0;k<16;k++){
            float4 a0 = *(const float4*)&sA[k*132 + ty*8];
            float4 a1 = *(const float4*)&sA[k*132 + ty*8 + 4];
            ulonglong2 b0 = *(const ulonglong2*)&sB[k*132 + tx*8];
            ulonglong2 b1 = *(const ulonglong2*)&sB[k*132 + tx*8 + 4];
            unsigned long long bp0=b0.x, bp1=b0.y, bp2=b1.x, bp3=b1.y;
            float ar[8] = {a0.x,a0.y,a0.z,a0.w,a1.x,a1.y,a1.z,a1.w};
            #pragma unroll
            for (int r=0;r<8;r++){
                unsigned long long a2 = pack2(ar[r]);
                fma2(acc[r][0], a2, bp0);
                fma2(acc[r][1], a2, bp1);
                fma2(acc[r][2], a2, bp2);
                fma2(acc[r][3], a2, bp3);
            }
        }
    }
    float4 ws0 = *(const float4*)&asv[tx*8];
    float4 ws1 = *(const float4*)&asv[tx*8+4];
    float4 wd0 = *(const float4*)&adv[tx*8];
    float4 wd1 = *(const float4*)&adv[tx*8+4];
    int hh = tx >> 2;
    #pragma unroll
    for (int r=0;r<8;r++){
        int node = n0 + ty*8 + r;
        if (node < NN){
            float f0=lo2(acc[r][0]), f1=hi2(acc[r][0]);
            float f2=lo2(acc[r][1]), f3=hi2(acc[r][1]);
            float f4=lo2(acc[r][2]), f5=hi2(acc[r][2]);
            float f6=lo2(acc[r][3]), f7=hi2(acc[r][3]);
            ulonglong2 v0; v0.x = acc[r][0]; v0.y = acc[r][1];
            ulonglong2 v1; v1.x = acc[r][2]; v1.y = acc[r][3];
            *(ulonglong2*)&g_xs[node*128 + tx*8]     = v0;
            *(ulonglong2*)&g_xs[node*128 + tx*8 + 4] = v1;
            float s = f0*ws0.x + f1*ws0.y + f2*ws0.z + f3*ws0.w
                    + f4*ws1.x + f5*ws1.y + f6*ws1.z + f7*ws1.w;
            float d = f0*wd0.x + f1*wd0.y + f2*wd0.z + f3*wd0.w
                    + f4*wd1.x + f5*wd1.y + f6*wd1.z + f7*wd1.w;
            s += __shfl_xor_sync(0xffffffffu, s, 1);
            s += __shfl_xor_sync(0xffffffffu, s, 2);
            d += __shfl_xor_sync(0xffffffffu, d, 1);
            d += __shfl_xor_sync(0xffffffffu, d, 2);
            if ((tx & 3) == 0){
                g_asrc[node*4+hh] = s;
                g_adst[node*4+hh] = d;
            }
        }
    }
}

// ---------------- collapsed output: logits + log_softmax ----------------
__global__ void k_out(float* __restrict__ out){
    __shared__ float sCW[5*384];
    __shared__ float sCB[5];
    int tid = threadIdx.x;
    for (int i=tid;i<1920;i+=256) sCW[i] = g_CW[i];
    if (tid < 5) sCB[tid] = g_cb2[tid];
    __syncthreads();
    int node = blockIdx.x*8 + (tid>>5);
    if (node >= NN) return;
    int lane = tid & 31;
    float4 a0 = ((const float4*)g_h0)[node*32+lane];
    float4 a1 = ((const float4*)g_h1)[node*32+lane];
    float4 a2 = ((const float4*)g_h2)[node*32+lane];
    float lg[5];
    #pragma unroll
    for (int c=0;c<5;c++){
        const float* w = &sCW[c*384];
        float4 b0 = *(const float4*)&w[lane*4];
        float4 b1 = *(const float4*)&w[128 + lane*4];
        float4 b2 = *(const float4*)&w[256 + lane*4];
        float p = a0.x*b0.x + a0.y*b0.y + a0.z*b0.z + a0.w*b0.w;
        p = fmaf(a1.x,b1.x, fmaf(a1.y,b1.y, fmaf(a1.z,b1.z, fmaf(a1.w,b1.w, p))));
        p = fmaf(a2.x,b2.x, fmaf(a2.y,b2.y, fmaf(a2.z,b2.z, fmaf(a2.w,b2.w, p))));
        #pragma unroll
        for (int o=16;o>0;o>>=1) p += __shfl_xor_sync(0xffffffffu, p, o);
        lg[c] = p + sCB[c];
    }
    if (lane == 0){
        float m = lg[0];
        #pragma unroll
        for (int c=1;c<5;c++) m = fmaxf(m, lg[c]);
        float s = 0.f;
        #pragma unroll
        for (int c=0;c<5;c++) s += __expf(lg[c]-m);
        float ls = logf(s);
        #pragma unroll
        for (int c=0;c<5;c++) out[node*5+c] = lg[c]-m-ls;
    }
}

// ---------------- launcher ----------------
extern "C" void kernel_launch(void* const* d_in, const int* in_sizes, int n_in,
                              void* d_out, int out_size){
    const float* x      = (const float*)d_in[0];
    const int*   ei     = (const int*)  d_in[1];
    const float* ea     = (const float*)d_in[2];
    const float* ee_w1  = (const float*)d_in[3];
    const float* ee_b1  = (const float*)d_in[4];
    const float* ee_w2  = (const float*)d_in[5];
    const float* ee_b2  = (const float*)d_in[6];
    const float* proj_w = (const float*)d_in[7];
    const float* proj_b = (const float*)d_in[8];
    const float* c1_lin = (const float*)d_in[9];
    const float* c1_as  = (const float*)d_in[10];
    const float* c1_ad  = (const float*)d_in[11];
    const float* c1_le  = (const float*)d_in[12];
    const float* c1_ae  = (const float*)d_in[13];
    const float* c1_b   = (const float*)d_in[14];
    const float* c2_lin = (const float*)d_in[15];
    const float* c2_as  = (const float*)d_in[16];
    const float* c2_ad  = (const float*)d_in[17];
    const float* c2_le  = (const float*)d_in[18];
    const float* c2_ae  = (const float*)d_in[19];
    const float* c2_b   = (const float*)d_in[20];
    const float* n1_g   = (const float*)d_in[21];
    const float* n1_b   = (const float*)d_in[22];
    const float* n2_g   = (const float*)d_in[23];
    const float* n2_b   = (const float*)d_in[24];
    const float* jk_w   = (const float*)d_in[25];
    const float* jk_b   = (const float*)d_in[26];
    const float* cls_w  = (const float*)d_in[27];
    const float* cls_b  = (const float*)d_in[28];
    float* out = (float*)d_out;

    k_fused1<<<B_HIST+B_CW+1+B_NODE1,256>>>(ei, c1_le, c1_ae, c2_le, c2_ae,
                                            cls_w, cls_b, jk_w, jk_b,
                                            x, proj_w, proj_b, c1_lin, c1_as, c1_ad);
    k_scana<<<98,512>>>();
    k_scanb<<<1,128>>>();
    k_scanc<<<98,512>>>();
    k_edge<<<(QSTRIDE+255)/256,256>>>(ea, ei, ee_w1, ee_b1, ee_w2, ee_b2);
    k_gat<<<(NN+15)/16,512>>>(c1_b, n1_g, n1_b, 0);
    k_node2<<<(NN+127)/128,256>>>(c2_lin, c2_as, c2_ad);
    k_gat<<<(NN+15)/16,512>>>(c2_b, n2_g, n2_b, 1);
    k_out<<<(NN+7)/8,256>>>(out);
}

// round 10
// speedup vs baseline: 1.3553x; 1.0166x over previous
#include <cuda_runtime.h>
#include <cuda_fp16.h>
#include <math.h>

#define NN 50000
#define EE 800000

// ---------------- scratch (device globals; zero-initialized at load) ----------------
__device__ float  g_sae1[EE*4];   // a_edge (conv1) in CSR order
__device__ float  g_sae2[EE*4];   // a_edge (conv2) in CSR order
__device__ int    g_ssrc[EE];     // src node in CSR order
__device__ int    g_cnt[NN];      // invariant: zero at kernel_launch entry (scanc re-zeroes)
__device__ int    g_cur[NN];
__device__ int    g_rowptr[NN+1];
__device__ int    g_part[128];
__device__ float  g_h0[NN*128];
__device__ float  g_h1[NN*128];
__device__ float  g_h2[NN*128];
__device__ __half g_xsh[NN*128];  // fp16 copy of transformed features (gather source)
__device__ float  g_asrc[NN*4];
__device__ float  g_adst[NN*4];
__device__ float  g_M[32];        // [conv*16 + j*4 + h]
__device__ float  g_CW[5*384];    // collapsed classifier: cls_w @ jk_w
__device__ float  g_cb2[5];       // collapsed bias

// ---------------- packed f32x2 helpers ----------------
__device__ __forceinline__ unsigned long long pack2(float x){
    unsigned long long r;
    unsigned int u = __float_as_uint(x);
    asm("mov.b64 %0, {%1, %1};" : "=l"(r) : "r"(u));
    return r;
}
__device__ __forceinline__ void fma2(unsigned long long& acc,
                                     unsigned long long a, unsigned long long b){
    asm("fma.rn.f32x2 %0, %1, %2, %0;" : "+l"(acc) : "l"(a), "l"(b));
}
__device__ __forceinline__ float lo2(unsigned long long v){
    unsigned int a, b;
    asm("mov.b64 {%0, %1}, %2;" : "=r"(a), "=r"(b) : "l"(v));
    return __uint_as_float(a);
}
__device__ __forceinline__ float hi2(unsigned long long v){
    unsigned int a, b;
    asm("mov.b64 {%0, %1}, %2;" : "=r"(a), "=r"(b) : "l"(v));
    return __uint_as_float(b);
}
__device__ __forceinline__ unsigned h2u(__half2 h){
    return *reinterpret_cast<unsigned*>(&h);
}

// ============ launch 1: hist + CW-prep + M-prep + node1, fused ============
#define B_HIST 782
#define B_CW   241
#define B_NODE1 1563

__global__ void __launch_bounds__(256) k_fused1(
        const int* __restrict__ ei,
        const float* __restrict__ le1, const float* __restrict__ ae1,
        const float* __restrict__ le2, const float* __restrict__ ae2,
        const float* __restrict__ cw,  const float* __restrict__ cb,
        const float* __restrict__ jkw, const float* __restrict__ jkb,
        const float* __restrict__ x,
        const float* __restrict__ pw, const float* __restrict__ pb,
        const float* __restrict__ lw,
        const float* __restrict__ asv, const float* __restrict__ adv){
    int b = blockIdx.x;
    if (b < B_HIST){
        int t = b*256 + threadIdx.x;
        if (t < EE/4){
            int4 d4 = ((const int4*)(ei+EE))[t];
            atomicAdd(&g_cnt[d4.x], 1);
            atomicAdd(&g_cnt[d4.y], 1);
            atomicAdd(&g_cnt[d4.z], 1);
            atomicAdd(&g_cnt[d4.w], 1);
        }
        return;
    }
    if (b < B_HIST + B_CW){
        int w = (b-B_HIST)*8 + (threadIdx.x >> 5);
        int lane = threadIdx.x & 31;
        if (w >= 5*385) return;
        int c = w / 385, j = w % 385;
        float4 a = *(const float4*)&cw[c*128 + lane*4];
        int d = lane*4;
        float s;
        if (j < 384){
            s = a.x*jkw[(d+0)*384+j] + a.y*jkw[(d+1)*384+j]
              + a.z*jkw[(d+2)*384+j] + a.w*jkw[(d+3)*384+j];
        } else {
            float4 bb = *(const float4*)&jkb[d];
            s = a.x*bb.x + a.y*bb.y + a.z*bb.z + a.w*bb.w;
        }
        #pragma unroll
        for (int o=16;o>0;o>>=1) s += __shfl_xor_sync(0xffffffffu, s, o);
        if (lane == 0){
            if (j < 384) g_CW[c*384+j] = s;
            else         g_cb2[c] = s + cb[c];
        }
        return;
    }
    if (b == B_HIST + B_CW){
        int t = threadIdx.x;
        if (t < 32){
            int which = t >> 4, j = (t >> 2) & 3, h = t & 3;
            const float* le = which ? le2 : le1;
            const float* ae = which ? ae2 : ae1;
            float s = 0.f;
            for (int c = 0; c < 32; c++)
                s += le[(h*32+c)*4 + j] * ae[h*32+c];
            g_M[which*16 + j*4 + h] = s;
        }
        return;
    }
    // ---- node1: two independent 128-thread halves ----
    __shared__ __align__(16) float sx[2][16*20];
    int tid = threadIdx.x;
    int sub = tid >> 7, stid = tid & 127;
    int n0 = (b - (B_HIST+B_CW+1))*32 + sub*16;
    float attS = asv[stid], attD = adv[stid], pbd = pb[stid];
    float wp[16], wl[16];
    #pragma unroll
    for (int q=0;q<4;q++){
        float4 a = *(const float4*)&pw[stid*16 + q*4];
        wp[q*4+0]=a.x; wp[q*4+1]=a.y; wp[q*4+2]=a.z; wp[q*4+3]=a.w;
        float4 bb = *(const float4*)&lw[stid*16 + q*4];
        wl[q*4+0]=bb.x; wl[q*4+1]=bb.y; wl[q*4+2]=bb.z; wl[q*4+3]=bb.w;
    }
    for (int i=stid;i<256;i+=128){
        int n=i>>4, k=i&15;
        int node=n0+n;
        sx[sub][n*20+k] = (node<NN) ? x[node*16+k] : 0.f;
    }
    __syncthreads();
    float acc0[16], acc1[16];
    #pragma unroll
    for (int n=0;n<16;n++){ acc0[n]=pbd; acc1[n]=0.f; }
    #pragma unroll
    for (int n=0;n<16;n++){
        float4 x0 = *(const float4*)&sx[sub][n*20];
        float4 x1 = *(const float4*)&sx[sub][n*20+4];
        float4 x2 = *(const float4*)&sx[sub][n*20+8];
        float4 x3 = *(const float4*)&sx[sub][n*20+12];
        float xv[16] = {x0.x,x0.y,x0.z,x0.w, x1.x,x1.y,x1.z,x1.w,
                        x2.x,x2.y,x2.z,x2.w, x3.x,x3.y,x3.z,x3.w};
        #pragma unroll
        for (int k=0;k<16;k++){
            acc0[n] = fmaf(xv[k], wp[k], acc0[n]);
            acc1[n] = fmaf(xv[k], wl[k], acc1[n]);
        }
    }
    int lane = stid&31, h = stid>>5;
    for (int n=0;n<16;n++){
        int node=n0+n;
        if (node>=NN) break;
        g_h0[node*128+stid]  = acc0[n];
        g_xsh[node*128+stid] = __float2half(acc1[n]);
        float s = acc1[n]*attS, dd = acc1[n]*attD;
        #pragma unroll
        for (int o=16;o>0;o>>=1){
            s  += __shfl_down_sync(0xffffffffu, s, o);
            dd += __shfl_down_sync(0xffffffffu, dd, o);
        }
        if (lane==0){ g_asrc[node*4+h]=s; g_adst[node*4+h]=dd; }
    }
}

// ---------------- multi-block scan (3 tiny kernels) ----------------
__global__ void __launch_bounds__(512) k_scana(){
    __shared__ int sred[16];
    int t = blockIdx.x*512 + threadIdx.x;
    int v = (t < NN) ? g_cnt[t] : 0;
    #pragma unroll
    for (int o=16;o>0;o>>=1) v += __shfl_xor_sync(0xffffffffu, v, o);
    int lane = threadIdx.x & 31, wid = threadIdx.x >> 5;
    if (lane == 0) sred[wid] = v;
    __syncthreads();
    if (threadIdx.x < 16){
        v = sred[threadIdx.x];
        #pragma unroll
        for (int o=8;o>0;o>>=1) v += __shfl_xor_sync(0xffffu, v, o);
        if (threadIdx.x == 0) g_part[blockIdx.x] = v;
    }
}

__global__ void __launch_bounds__(128) k_scanb(){
    __shared__ int s[128];
    int t = threadIdx.x;
    int v = (t < 98) ? g_part[t] : 0;
    s[t] = v;
    __syncthreads();
    for (int off=1; off<128; off<<=1){
        int u = (t >= off) ? s[t-off] : 0;
        __syncthreads();
        s[t] += u;
        __syncthreads();
    }
    if (t < 98) g_part[t] = s[t] - v;   // exclusive
}

__global__ void __launch_bounds__(512) k_scanc(){
    __shared__ int s[512];
    int t = blockIdx.x*512 + threadIdx.x;
    int v = (t < NN) ? g_cnt[t] : 0;
    s[threadIdx.x] = v;
    __syncthreads();
    for (int off=1; off<512; off<<=1){
        int u = (threadIdx.x >= off) ? s[threadIdx.x-off] : 0;
        __syncthreads();
        s[threadIdx.x] += u;
        __syncthreads();
    }
    int excl = s[threadIdx.x] - v + g_part[blockIdx.x];
    if (t < NN){
        g_rowptr[t] = excl;
        g_cur[t]    = excl;
        g_cnt[t]    = 0;                // restore zero-invariant for graph replay
        if (t == NN-1) g_rowptr[NN] = excl + v;
    }
}

// ---------------- edge encoder: 4 edges/thread, WM-folded, coalesced ----------------
#define QSTRIDE 200000   // EE/4
__global__ void __launch_bounds__(256) k_edge(
        const float* __restrict__ ea, const int* __restrict__ ei,
        const float* __restrict__ w1, const float* __restrict__ b1,
        const float* __restrict__ w2, const float* __restrict__ b2){
    __shared__ __align__(16) float sw1[256];
    __shared__ float sb1[32];
    __shared__ __align__(16) float sWM1[128];  // [c][h] = sum_j w2[j][c]*M1[j][h]
    __shared__ __align__(16) float sWM2[128];
    __shared__ float sR0[8];                   // b2 @ M1, b2 @ M2
    int tid = threadIdx.x;
    if (tid < 256) sw1[tid] = w1[tid];
    if (tid < 32)  sb1[tid] = b1[tid];
    if (tid < 128){
        int c = tid >> 2, h = tid & 3;
        float s1 = 0.f, s2 = 0.f;
        #pragma unroll
        for (int j=0;j<4;j++){
            float wv = w2[j*32+c];
            s1 = fmaf(wv, g_M[j*4+h],    s1);
            s2 = fmaf(wv, g_M[16+j*4+h], s2);
        }
        sWM1[c*4+h] = s1;
        sWM2[c*4+h] = s2;
    }
    if (tid >= 128 && tid < 136){
        int which = (tid-128) >> 2, h = tid & 3;
        float s = 0.f;
        #pragma unroll
        for (int j=0;j<4;j++) s = fmaf(b2[j], g_M[which*16+j*4+h], s);
        sR0[tid-128] = s;
    }
    __syncthreads();
    int gid = blockIdx.x*256 + tid;
    if (gid >= QSTRIDE) return;
    float4 A[4][2];
    #pragma unroll
    for (int q=0;q<4;q++){
        int e = gid + q*QSTRIDE;
        A[q][0] = ((const float4*)ea)[e*2];
        A[q][1] = ((const float4*)ea)[e*2+1];
    }
    float4 R10 = *(const float4*)&sR0[0];
    float4 R20 = *(const float4*)&sR0[4];
    float4 r1[4], r2[4];
    #pragma unroll
    for (int q=0;q<4;q++){ r1[q]=R10; r2[q]=R20; }
    #pragma unroll
    for (int c=0;c<32;c++){
        float4 wa = *(const float4*)&sw1[c*8];
        float4 wb = *(const float4*)&sw1[c*8+4];
        float bc  = sb1[c];
        float4 m1 = *(const float4*)&sWM1[c*4];
        float4 m2 = *(const float4*)&sWM2[c*4];
        #pragma unroll
        for (int q=0;q<4;q++){
            float hv = bc;
            hv = fmaf(wa.x, A[q][0].x, hv); hv = fmaf(wa.y, A[q][0].y, hv);
            hv = fmaf(wa.z, A[q][0].z, hv); hv = fmaf(wa.w, A[q][0].w, hv);
            hv = fmaf(wb.x, A[q][1].x, hv); hv = fmaf(wb.y, A[q][1].y, hv);
            hv = fmaf(wb.z, A[q][1].z, hv); hv = fmaf(wb.w, A[q][1].w, hv);
            hv = fmaxf(hv, 0.f);
            r1[q].x = fmaf(m1.x, hv, r1[q].x);
            r1[q].y = fmaf(m1.y, hv, r1[q].y);
            r1[q].z = fmaf(m1.z, hv, r1[q].z);
            r1[q].w = fmaf(m1.w, hv, r1[q].w);
            r2[q].x = fmaf(m2.x, hv, r2[q].x);
            r2[q].y = fmaf(m2.y, hv, r2[q].y);
            r2[q].z = fmaf(m2.z, hv, r2[q].z);
            r2[q].w = fmaf(m2.w, hv, r2[q].w);
        }
    }
    #pragma unroll
    for (int q=0;q<4;q++){
        int e = gid + q*QSTRIDE;
        int srcn = ei[e], d = ei[EE+e];
        int pos = atomicAdd(&g_cur[d], 1);
        g_ssrc[pos] = srcn;
        ((float4*)g_sae1)[pos] = r1[q];
        ((float4*)g_sae2)[pos] = r2[q];
    }
}

// ---------------- fused GAT conv (fp16 gather) + (conv2) JK/classifier/log_softmax ----------------
__global__ void __launch_bounds__(512) k_gat(const float* __restrict__ bias,
                      const float* __restrict__ gam,
                      const float* __restrict__ bet, int conv,
                      float* __restrict__ out){
    __shared__ float2 sp[16][132];   // [warp][h*33 + j], stride 33 => conflict-free
    __shared__ float sCW[1920];
    __shared__ float sCB[5];
    int tid = threadIdx.x;
    if (conv){
        for (int i=tid;i<1920;i+=512) sCW[i] = g_CW[i];
        if (tid < 5) sCB[tid] = g_cb2[tid];
    }
    __syncthreads();
    int wid = tid >> 5, lane = tid & 31;
    int node = blockIdx.x*16 + wid;
    if (node >= NN) return;
    int h = lane >> 3;
    const float4* __restrict__ sae   = (const float4*)(conv ? g_sae2 : g_sae1);
    const float4* __restrict__ asrc4 = (const float4*)g_asrc;
    const char*   xbase = ((const char*)g_xsh) + lane*8;
    float4 ad = ((const float4*)g_adst)[node];
    int beg = g_rowptr[node], end = g_rowptr[node+1];
    float4 den = make_float4(0.f,0.f,0.f,0.f);
    float4 acc = make_float4(0.f,0.f,0.f,0.f);
    for (int base = beg; base < end; base += 32){
        int idx = base + lane;
        bool v = idx < end;
        int s = g_ssrc[v ? idx : end-1];
        float4 w = make_float4(0.f,0.f,0.f,0.f);
        if (v){
            float4 ae = sae[idx];
            float4 as = asrc4[s];
            float ax = as.x+ad.x+ae.x; ax = ax>0.f?ax:0.2f*ax;
            float ay = as.y+ad.y+ae.y; ay = ay>0.f?ay:0.2f*ay;
            float az = as.z+ad.z+ae.z; az = az>0.f?az:0.2f*az;
            float aw = as.w+ad.w+ae.w; aw = aw>0.f?aw:0.2f*aw;
            w = make_float4(__expf(ax), __expf(ay), __expf(az), __expf(aw));
        }
        den.x += w.x; den.y += w.y; den.z += w.z; den.w += w.w;
        float so = __uint_as_float((unsigned)s * 256u);   // byte offset of fp16 row
        __syncwarp();
        sp[wid][lane]       = make_float2(so, w.x);
        sp[wid][33 + lane]  = make_float2(so, w.y);
        sp[wid][66 + lane]  = make_float2(so, w.z);
        sp[wid][99 + lane]  = make_float2(so, w.w);
        __syncwarp();
        int cnt = end - base; if (cnt > 32) cnt = 32;
        const float2* hp2 = &sp[wid][h*33];
        for (int c = 0; c < cnt; c += 8){
            #pragma unroll
            for (int j = 0; j < 8; j++){
                float2 e2 = hp2[c+j];
                uint2 xraw = *(const uint2*)(xbase + __float_as_uint(e2.x));
                float2 f0 = __half22float2(*reinterpret_cast<__half2*>(&xraw.x));
                float2 f1 = __half22float2(*reinterpret_cast<__half2*>(&xraw.y));
                acc.x = fmaf(e2.y, f0.x, acc.x);
                acc.y = fmaf(e2.y, f0.y, acc.y);
                acc.z = fmaf(e2.y, f1.x, acc.z);
                acc.w = fmaf(e2.y, f1.y, acc.w);
            }
        }
    }
    #pragma unroll
    for (int o=16;o>0;o>>=1){
        den.x += __shfl_xor_sync(0xffffffffu, den.x, o);
        den.y += __shfl_xor_sync(0xffffffffu, den.y, o);
        den.z += __shfl_xor_sync(0xffffffffu, den.z, o);
        den.w += __shfl_xor_sync(0xffffffffu, den.w, o);
    }
    float dh = (h==0)?den.x:(h==1)?den.y:(h==2)?den.z:den.w;
    float inv = 1.f/(dh + 1e-16f);
    const float* hp = conv ? g_h1 : g_h0;
    float*       ho = conv ? g_h2 : g_h1;
    float4 hv = ((const float4*)hp)[node*32+lane];
    float4 bv = *(const float4*)&bias[lane*4];
    float4 r;
    r.x = acc.x*inv + bv.x; r.x = (r.x>0.f)?r.x:(__expf(r.x)-1.f); r.x += hv.x;
    r.y = acc.y*inv + bv.y; r.y = (r.y>0.f)?r.y:(__expf(r.y)-1.f); r.y += hv.y;
    r.z = acc.z*inv + bv.z; r.z = (r.z>0.f)?r.z:(__expf(r.z)-1.f); r.z += hv.z;
    r.w = acc.w*inv + bv.w; r.w = (r.w>0.f)?r.w:(__expf(r.w)-1.f); r.w += hv.w;
    float s1 = r.x+r.y+r.z+r.w;
    float s2 = r.x*r.x + r.y*r.y + r.z*r.z + r.w*r.w;
    #pragma unroll
    for (int o=16;o>0;o>>=1){
        s1 += __shfl_xor_sync(0xffffffffu, s1, o);
        s2 += __shfl_xor_sync(0xffffffffu, s2, o);
    }
    float mu  = s1 * (1.f/128.f);
    float var = s2 * (1.f/128.f) - mu*mu;
    float rs  = rsqrtf(var + 1e-5f);
    float4 gv = *(const float4*)&gam[lane*4];
    float4 be = *(const float4*)&bet[lane*4];
    float4 o4;
    o4.x = (r.x-mu)*rs*gv.x + be.x;
    o4.y = (r.y-mu)*rs*gv.y + be.y;
    o4.z = (r.z-mu)*rs*gv.z + be.z;
    o4.w = (r.w-mu)*rs*gv.w + be.w;
    ((float4*)ho)[node*32+lane] = o4;

    if (conv){
        // fused JK-collapsed classifier + log_softmax (h0 = load, h1 = hv, h2 = o4)
        float4 a0 = ((const float4*)g_h0)[node*32+lane];
        float lg[5];
        #pragma unroll
        for (int c=0;c<5;c++){
            const float* w = &sCW[c*384];
            float4 b0 = *(const float4*)&w[lane*4];
            float4 b1 = *(const float4*)&w[128 + lane*4];
            float4 b2 = *(const float4*)&w[256 + lane*4];
            float p = a0.x*b0.x + a0.y*b0.y + a0.z*b0.z + a0.w*b0.w;
            p = fmaf(hv.x,b1.x, fmaf(hv.y,b1.y, fmaf(hv.z,b1.z, fmaf(hv.w,b1.w, p))));
            p = fmaf(o4.x,b2.x, fmaf(o4.y,b2.y, fmaf(o4.z,b2.z, fmaf(o4.w,b2.w, p))));
            #pragma unroll
            for (int o=16;o>0;o>>=1) p += __shfl_xor_sync(0xffffffffu, p, o);
            lg[c] = p + sCB[c];
        }
        if (lane == 0){
            float m = lg[0];
            #pragma unroll
            for (int c=1;c<5;c++) m = fmaxf(m, lg[c]);
            float s = 0.f;
            #pragma unroll
            for (int c=0;c<5;c++) s += __expf(lg[c]-m);
            float ls = logf(s);
            #pragma unroll
            for (int c=0;c<5;c++) out[node*5+c] = lg[c]-m-ls;
        }
    }
}

// ---------------- conv2 GEMM + fused attention dots (fp16 xs output) ----------------
__global__ void __launch_bounds__(256) k_node2(const float* __restrict__ lin,
                                               const float* __restrict__ asv,
                                               const float* __restrict__ adv){
    __shared__ float sA[16*132];
    __shared__ float sB[16*132];
    int tid = threadIdx.x;
    int tx = tid & 15, ty = tid >> 4;
    int n0 = blockIdx.x*128;
    unsigned long long acc[8][4];
    #pragma unroll
    for (int r=0;r<8;r++)
        #pragma unroll
        for (int p=0;p<4;p++) acc[r][p] = 0ULL;
    for (int kc=0;kc<8;kc++){
        __syncthreads();
        #pragma unroll
        for (int t=tid;t<512;t+=256){
            int r = t>>2, q = t&3;
            int node = n0 + r;
            float4 v = (node<NN) ? *(const float4*)&g_h1[node*128 + kc*16 + q*4]
                                 : make_float4(0.f,0.f,0.f,0.f);
            sA[(q*4+0)*132+r]=v.x; sA[(q*4+1)*132+r]=v.y;
            sA[(q*4+2)*132+r]=v.z; sA[(q*4+3)*132+r]=v.w;
        }
        #pragma unroll
        for (int t=tid;t<512;t+=256){
            int d = t>>2, q = t&3;
            float4 v = *(const float4*)&lin[d*128 + kc*16 + q*4];
            sB[(q*4+0)*132+d]=v.x; sB[(q*4+1)*132+d]=v.y;
            sB[(q*4+2)*132+d]=v.z; sB[(q*4+3)*132+d]=v.w;
        }
        __syncthreads();
        #pragma unroll
        for (int k=0;k<16;k++){
            float4 a0 = *(const float4*)&sA[k*132 + ty*8];
            float4 a1 = *(const float4*)&sA[k*132 + ty*8 + 4];
            ulonglong2 b0 = *(const ulonglong2*)&sB[k*132 + tx*8];
            ulonglong2 b1 = *(const ulonglong2*)&sB[k*132 + tx*8 + 4];
            unsigned long long bp0=b0.x, bp1=b0.y, bp2=b1.x, bp3=b1.y;
            float ar[8] = {a0.x,a0.y,a0.z,a0.w,a1.x,a1.y,a1.z,a1.w};
            #pragma unroll
            for (int r=0;r<8;r++){
                unsigned long long a2 = pack2(ar[r]);
                fma2(acc[r][0], a2, bp0);
                fma2(acc[r][1], a2, bp1);
                fma2(acc[r][2], a2, bp2);
                fma2(acc[r][3], a2, bp3);
            }
        }
    }
    float4 ws0 = *(const float4*)&asv[tx*8];
    float4 ws1 = *(const float4*)&asv[tx*8+4];
    float4 wd0 = *(const float4*)&adv[tx*8];
    float4 wd1 = *(const float4*)&adv[tx*8+4];
    int hh = tx >> 2;
    #pragma unroll
    for (int r=0;r<8;r++){
        int node = n0 + ty*8 + r;
        if (node < NN){
            float f0=lo2(acc[r][0]), f1=hi2(acc[r][0]);
            float f2=lo2(acc[r][1]), f3=hi2(acc[r][1]);
            float f4=lo2(acc[r][2]), f5=hi2(acc[r][2]);
            float f6=lo2(acc[r][3]), f7=hi2(acc[r][3]);
            uint4 st;
            st.x = h2u(__floats2half2_rn(f0, f1));
            st.y = h2u(__floats2half2_rn(f2, f3));
            st.z = h2u(__floats2half2_rn(f4, f5));
            st.w = h2u(__floats2half2_rn(f6, f7));
            *(uint4*)(((char*)g_xsh) + node*256 + tx*16) = st;
            float s = f0*ws0.x + f1*ws0.y + f2*ws0.z + f3*ws0.w
                    + f4*ws1.x + f5*ws1.y + f6*ws1.z + f7*ws1.w;
            float d = f0*wd0.x + f1*wd0.y + f2*wd0.z + f3*wd0.w
                    + f4*wd1.x + f5*wd1.y + f6*wd1.z + f7*wd1.w;
            s += __shfl_xor_sync(0xffffffffu, s, 1);
            s += __shfl_xor_sync(0xffffffffu, s, 2);
            d += __shfl_xor_sync(0xffffffffu, d, 1);
            d += __shfl_xor_sync(0xffffffffu, d, 2);
            if ((tx & 3) == 0){
                g_asrc[node*4+hh] = s;
                g_adst[node*4+hh] = d;
            }
        }
    }
}

// ---------------- launcher ----------------
extern "C" void kernel_launch(void* const* d_in, const int* in_sizes, int n_in,
                              void* d_out, int out_size){
    const float* x      = (const float*)d_in[0];
    const int*   ei     = (const int*)  d_in[1];
    const float* ea     = (const float*)d_in[2];
    const float* ee_w1  = (const float*)d_in[3];
    const float* ee_b1  = (const float*)d_in[4];
    const float* ee_w2  = (const float*)d_in[5];
    const float* ee_b2  = (const float*)d_in[6];
    const float* proj_w = (const float*)d_in[7];
    const float* proj_b = (const float*)d_in[8];
    const float* c1_lin = (const float*)d_in[9];
    const float* c1_as  = (const float*)d_in[10];
    const float* c1_ad  = (const float*)d_in[11];
    const float* c1_le  = (const float*)d_in[12];
    const float* c1_ae  = (const float*)d_in[13];
    const float* c1_b   = (const float*)d_in[14];
    const float* c2_lin = (const float*)d_in[15];
    const float* c2_as  = (const float*)d_in[16];
    const float* c2_ad  = (const float*)d_in[17];
    const float* c2_le  = (const float*)d_in[18];
    const float* c2_ae  = (const float*)d_in[19];
    const float* c2_b   = (const float*)d_in[20];
    const float* n1_g   = (const float*)d_in[21];
    const float* n1_b   = (const float*)d_in[22];
    const float* n2_g   = (const float*)d_in[23];
    const float* n2_b   = (const float*)d_in[24];
    const float* jk_w   = (const float*)d_in[25];
    const float* jk_b   = (const float*)d_in[26];
    const float* cls_w  = (const float*)d_in[27];
    const float* cls_b  = (const float*)d_in[28];
    float* out = (float*)d_out;

    k_fused1<<<B_HIST+B_CW+1+B_NODE1,256>>>(ei, c1_le, c1_ae, c2_le, c2_ae,
                                            cls_w, cls_b, jk_w, jk_b,
                                            x, proj_w, proj_b, c1_lin, c1_as, c1_ad);
    k_scana<<<98,512>>>();
    k_scanb<<<1,128>>>();
    k_scanc<<<98,512>>>();
    k_edge<<<(QSTRIDE+255)/256,256>>>(ea, ei, ee_w1, ee_b1, ee_w2, ee_b2);
    k_gat<<<(NN+15)/16,512>>>(c1_b, n1_g, n1_b, 0, out);
    k_node2<<<(NN+127)/128,256>>>(c2_lin, c2_as, c2_ad);
    k_gat<<<(NN+15)/16,512>>>(c2_b, n2_g, n2_b, 1, out);
}